// round 14
// baseline (speedup 1.0000x reference)
#include <cuda_runtime.h>

#define LN 2
#define NR 768
#define NA 14
#define TJ 32                       // j per block
#define TI 128                      // i per block (4 passes of 32)
#define NPASS (TI / 32)             // 4
#define NTJ (NR / TJ)               // 24
#define NTI (NR / TI)               // 6
#define NFAPE (NTI * NTJ * LN)      // 288 fape blocks
#define NLDDT 96                    // 96 lddt blocks x 8 rows
#define ROWS_PER_LDDT (NR / NLDDT)  // 8

// output layout: fape_loss[2], rotamer_loss[2], final_ae[768*768], rotamer_error[-1][768], lddt[768]
#define OFF_AE   4
#define OFF_RE   (4 + NR * NR)
#define OFF_LDDT (OFF_RE + NR)

// ---- device scratch (zero-initialized at load; re-zeroed by last block every run) ----
__device__ float    g_acc[9];   // intra0,intra1,inter0,inter1,cnt_s,cnt_o,diag0,diag1,nres
__device__ unsigned g_cnt;      // fape blocks done

__device__ __forceinline__ float sqrt_approx(float x) {
    float r; asm("sqrt.approx.f32 %0, %1;" : "=f"(r) : "f"(x)); return r;
}
__device__ __forceinline__ float rsqrt_approx(float x) {
    float r; asm("rsqrt.approx.f32 %0, %1;" : "=f"(r) : "f"(x)); return r;
}
__device__ __forceinline__ float warp_sum(float v) {
#pragma unroll
    for (int o = 16; o > 0; o >>= 1) v += __shfl_down_sync(0xffffffffu, v, o);
    return v;
}

__device__ __forceinline__ void make_frame(const float n[3], const float ca[3], const float c[3],
                                           float e1[3], float e2[3], float e3[3]) {
    e1[0] = c[0] - ca[0]; e1[1] = c[1] - ca[1]; e1[2] = c[2] - ca[2];
    float s1 = e1[0]*e1[0] + e1[1]*e1[1] + e1[2]*e1[2];
    float i1 = rsqrt_approx(fmaxf(s1, 1e-6f));
    e1[0] *= i1; e1[1] *= i1; e1[2] *= i1;
    float v2[3] = { n[0]-ca[0], n[1]-ca[1], n[2]-ca[2] };
    float dt = e1[0]*v2[0] + e1[1]*v2[1] + e1[2]*v2[2];
    e2[0] = v2[0] - dt*e1[0]; e2[1] = v2[1] - dt*e1[1]; e2[2] = v2[2] - dt*e1[2];
    float s2 = e2[0]*e2[0] + e2[1]*e2[1] + e2[2]*e2[2];
    float i2 = rsqrt_approx(fmaxf(s2, 1e-6f));
    e2[0] *= i2; e2[1] *= i2; e2[2] *= i2;
    e3[0] = e1[1]*e2[2] - e1[2]*e2[1];
    e3[1] = e1[2]*e2[0] - e1[0]*e2[2];
    e3[2] = e1[0]*e2[1] - e1[1]*e2[0];
}

__device__ __forceinline__ void compute_Qo(const float* __restrict__ pred,
                                           const float* __restrict__ gt,
                                           int l, int i, float* dst /*12 floats*/) {
    const float* gb = gt + (size_t)i * NA * 3;
    float gn[3]  = { gb[0], gb[1], gb[2] };
    float gca[3] = { gb[3], gb[4], gb[5] };
    float gc[3]  = { gb[6], gb[7], gb[8] };
    float e1g[3], e2g[3], e3g[3];
    make_frame(gn, gca, gc, e1g, e2g, e3g);

    const float* pb = pred + (size_t)(l * NR + i) * NA * 3;
    float pn[3]  = { pb[0], pb[1], pb[2] };
    float pca[3] = { pb[3], pb[4], pb[5] };
    float pc[3]  = { pb[6], pb[7], pb[8] };
    float e1p[3], e2p[3], e3p[3];
    make_frame(pn, pca, pc, e1p, e2p, e3p);

#pragma unroll
    for (int d = 0; d < 3; d++) {
        float q0 = e1p[d]*e1g[0] + e2p[d]*e2g[0] + e3p[d]*e3g[0];
        float q1 = e1p[d]*e1g[1] + e2p[d]*e2g[1] + e3p[d]*e3g[1];
        float q2 = e1p[d]*e1g[2] + e2p[d]*e2g[2] + e3p[d]*e3g[2];
        dst[3*d+0] = q0; dst[3*d+1] = q1; dst[3*d+2] = q2;
        dst[9 + d] = pca[d] - (q0*gca[0] + q1*gca[1] + q2*gca[2]);
    }
}

__device__ __forceinline__ int atom_bits(const float* __restrict__ am, int i) {
    const float2* r = (const float2*)(am + (size_t)i * NA);
    int bits = 0;
#pragma unroll
    for (int k = 0; k < 7; k++) {
        float2 f = r[k];
        if (f.x > 0.f) bits |= (1 << (2 * k));
        if (f.y > 0.f) bits |= (1 << (2 * k + 1));
    }
    return bits;
}

__device__ __forceinline__ void fape_done(float* __restrict__ out) {
    __threadfence();
    unsigned done = atomicAdd(&g_cnt, 1u);
    if (done == NFAPE - 1) {
        float nres = fmaxf(g_acc[8], 1e-6f);
        float invCS = 0.1f / fmaxf(g_acc[4], 1e-6f);
        float invCO = 0.1f / fmaxf(g_acc[5], 1e-6f);
        out[0] = g_acc[0] * invCS + g_acc[2] * invCO;  // fape_loss[0]
        out[1] = g_acc[1] * invCS + g_acc[3] * invCO;  // fape_loss[1]
        out[2] = g_acc[6] / nres;                      // rotamer_loss[0]
        out[3] = g_acc[7] / nres;                      // rotamer_loss[1]
#pragma unroll
        for (int k = 0; k < 9; k++) g_acc[k] = 0.f;    // reset for next replay
        __threadfence();
        g_cnt = 0u;
    }
}

// ---- single fused kernel: blocks [0,288) = fape (128i x 32j x one l), [288,384) = lddt ----
__global__ __launch_bounds__(256, 3) void fused_kernel(const float* __restrict__ pred,
                                                       const float* __restrict__ gt,
                                                       const float* __restrict__ am,
                                                       const int* __restrict__ batch,
                                                       const int* __restrict__ chain,
                                                       float* __restrict__ out) {
    const int tid = threadIdx.x;
    const int tx = tid & 31, ty = tid >> 5;
    const int b = blockIdx.x;

    if (b >= NFAPE) {
        // ================= lDDT: 96 blocks x 8 rows =================
        __shared__ float sg[NR][3];
        __shared__ float sp[NR][3];
        __shared__ int   srm[NR];
        __shared__ float lred[8][2];
        for (int j = tid; j < NR; j += 256) {
            const float* gp = gt + ((size_t)j * NA + 1) * 3;
            sg[j][0] = gp[0]; sg[j][1] = gp[1]; sg[j][2] = gp[2];
            const float* pp = pred + ((size_t)(1 * NR + j) * NA + 1) * 3;  // pred[-1]
            sp[j][0] = pp[0]; sp[j][1] = pp[1]; sp[j][2] = pp[2];
            srm[j] = (atom_bits(am, j) != 0);
        }
        __syncthreads();

        const int i0 = (b - NFAPE) * ROWS_PER_LDDT;
#pragma unroll
        for (int r = 0; r < ROWS_PER_LDDT; r++) {
            const int i = i0 + r;
            const float gix = sg[i][0], giy = sg[i][1], giz = sg[i][2];
            const float pix = sp[i][0], piy = sp[i][1], piz = sp[i][2];
            float suml = 0.f, cnt = 0.f;
            if (srm[i]) {
                for (int j = tid; j < NR; j += 256) {
                    if (j == i || !srm[j]) continue;
                    float dx = gix - sg[j][0], dy = giy - sg[j][1], dz = giz - sg[j][2];
                    float gd = sqrt_approx(fmaxf(dx*dx + dy*dy + dz*dz, 1e-6f));
                    if (gd < 15.f) {
                        float ex = pix - sp[j][0], ey = piy - sp[j][1], ez = piz - sp[j][2];
                        float d = sqrt_approx(fmaxf(ex*ex + ey*ey + ez*ez, 1e-6f));
                        float derr = fabsf(gd - d);
                        int c = (derr < 0.5f) + (derr < 1.0f) + (derr < 2.0f) + (derr < 4.0f);
                        suml += 0.25f * (float)c;
                        cnt  += 1.f;
                    }
                }
            }
            float v0 = warp_sum(suml), v1 = warp_sum(cnt);
            if (tx == 0) { lred[ty][0] = v0; lred[ty][1] = v1; }
            __syncthreads();
            if (tid == 0) {
                float s = 0.f, c = 0.f;
#pragma unroll
                for (int w = 0; w < 8; w++) { s += lred[w][0]; c += lred[w][1]; }
                out[OFF_LDDT + i] = s / fmaxf(c, 1e-6f);
            }
            __syncthreads();
        }
        return;
    }

    // ================= FAPE super-tile: 128 i x 32 j, one l =================
    const int l = b / (NTI * NTJ);
    const int t = b % (NTI * NTJ);
    const int i0 = (t / NTJ) * TI, j0 = (t % NTJ) * TJ;
    float* out_ae = out + OFF_AE;

    // uniform loads for skip decisions (L1 broadcast, no barrier); batch sorted
    const int bj0 = batch[j0], bj1 = batch[j0 + TJ - 1];
    bool skipP[NPASS];
    bool allSkip = true;
#pragma unroll
    for (int p = 0; p < NPASS; p++) {
        skipP[p] = (batch[i0 + 32 * p] > bj1) || (bj0 > batch[i0 + 32 * p + 31]);
        allSkip = allSkip && skipP[p];
    }

    if (allSkip) {
        if (l == 0 && j0 == 0 && tid < 32) {   // nres for all 4 row groups
            float n = 0.f;
#pragma unroll
            for (int p = 0; p < NPASS; p++)
                n += (atom_bits(am, i0 + 32 * p + tid) != 0) ? 1.f : 0.f;
            n = warp_sum(n);
            if (tid == 0) atomicAdd(&g_acc[8], n);
        }
        if (l == 1) {
#pragma unroll
            for (int r = 0; r < 16; r++)
                out_ae[(size_t)(i0 + ty + 8 * r) * NR + (j0 + tx)] = 0.f;
        }
        if (tid == 0) fape_done(out);
        return;
    }

    __shared__ float4 sP[TJ * 15];
    __shared__ float4 sG[TJ * 15];
    __shared__ float  sQ[TI * 12];
    __shared__ int    sBatI[TI], sBatJ[TJ], sBitI[TI], sBitJ[TJ], sChI[TI], sChJ[TJ];
    __shared__ float  sred[8][5];

    if (tid < TI) {
        compute_Qo(pred, gt, l, i0 + tid, &sQ[tid * 12]);
        sBatI[tid] = batch[i0 + tid];
        sChI[tid]  = chain[i0 + tid];
        sBitI[tid] = atom_bits(am, i0 + tid);
    } else if (tid < TI + TJ) {
        int u = tid - TI;
        sBatJ[u] = batch[j0 + u];
        sChJ[u]  = chain[j0 + u];
        sBitJ[u] = atom_bits(am, j0 + u);
    }
    for (int u = tid - (TI + TJ); u >= 0 && u < TJ * NA; u += 256 - TI - TJ) {
        int j = u / NA, a = u % NA;
        const float* pp = pred + ((size_t)(l * NR + j0 + j) * NA + a) * 3;
        sP[j * 15 + a] = make_float4(pp[0], pp[1], pp[2], 0.f);
        const float* gp = gt + ((size_t)(j0 + j) * NA + a) * 3;
        sG[j * 15 + a] = make_float4(gp[0], gp[1], gp[2], 0.f);
    }
    __syncthreads();

    // nres contribution (6 blocks: l==0, j_tile==0)
    if (l == 0 && j0 == 0 && tid < 32) {
        float n = 0.f;
#pragma unroll
        for (int p = 0; p < NPASS; p++)
            n += (sBitI[32 * p + tid] != 0) ? 1.f : 0.f;
        n = warp_sum(n);
        if (tid == 0) atomicAdd(&g_acc[8], n);
    }

    const int batJ = sBatJ[tx], bitJ = sBitJ[tx], chJ = sChJ[tx];
    float pIntra = 0.f, pInter = 0.f, pCntS = 0.f, pCntO = 0.f, pDiag = 0.f;

#pragma unroll 1
    for (int pass = 0; pass < NPASS; pass++) {
        if (skipP[pass]) {
            if (l == 1) {
#pragma unroll
                for (int r = 0; r < 4; r++)
                    out_ae[(size_t)(i0 + 32 * pass + ty + 8 * r) * NR + (j0 + tx)] = 0.f;
            }
            continue;
        }
        const int base = 32 * pass;

        float q[4][12];
        unsigned mb[4];
#pragma unroll
        for (int r = 0; r < 4; r++) {
            const int row = base + ty + 8 * r;
#pragma unroll
            for (int k = 0; k < 12; k++) q[r][k] = sQ[row * 12 + k];
            mb[r] = (sBatI[row] == batJ) ? (unsigned)(sBitI[row] & bitJ) : 0u;
        }

        float se[4] = {0.f, 0.f, 0.f, 0.f};
#pragma unroll
        for (int a = 0; a < NA; a++) {
            const float4 g = sG[tx * 15 + a];
            const float4 p = sP[tx * 15 + a];
#pragma unroll
            for (int r = 0; r < 4; r++) {
                float w0 = fmaf(q[r][0], g.x, fmaf(q[r][1], g.y, fmaf(q[r][2], g.z, q[r][9])));
                float w1 = fmaf(q[r][3], g.x, fmaf(q[r][4], g.y, fmaf(q[r][5], g.z, q[r][10])));
                float w2 = fmaf(q[r][6], g.x, fmaf(q[r][7], g.y, fmaf(q[r][8], g.z, q[r][11])));
                float d0 = p.x - w0, d1 = p.y - w1, d2 = p.z - w2;
                float n2 = fmaf(d0, d0, fmaf(d1, d1, d2 * d2));
                float err = sqrt_approx(fmaxf(n2, 1e-6f));
                se[r] += ((mb[r] >> a) & 1u) ? err : 0.f;
            }
        }

#pragma unroll
        for (int r = 0; r < 4; r++) {
            const int row = base + ty + 8 * r;
            const int i = i0 + row, j = j0 + tx;
            float fape = __fdividef(se[r], fmaxf((float)__popc(mb[r]), 1e-6f));
            if (l == 1) out_ae[(size_t)i * NR + j] = fape;
            if (mb[r] != 0u) {
                float clip = fminf(fape, 10.f);
                if (sChI[row] == chJ) { pIntra += clip; pCntS += 1.f; }
                else                  { pInter += clip; pCntO += 1.f; }
            }
            if (i == j) {
                pDiag += fape;
                if (l == 1) out[OFF_RE + i] = fape;
            }
        }
    }

    float vals[5] = { pIntra, pInter, pCntS, pCntO, pDiag };
#pragma unroll
    for (int k = 0; k < 5; k++) {
        float v = warp_sum(vals[k]);
        if (tx == 0) sred[ty][k] = v;
    }
    __syncthreads();
    if (tid < 5) {
        float v = 0.f;
#pragma unroll
        for (int w = 0; w < 8; w++) v += sred[w][tid];
        if (tid == 0) atomicAdd(&g_acc[0 + l], v);
        else if (tid == 1) atomicAdd(&g_acc[2 + l], v);
        else if (tid == 2) { if (l == 0) atomicAdd(&g_acc[4], v); }
        else if (tid == 3) { if (l == 0) atomicAdd(&g_acc[5], v); }
        else atomicAdd(&g_acc[6 + l], v);
    }

    __syncthreads();
    if (tid == 0) fape_done(out);
}

extern "C" void kernel_launch(void* const* d_in, const int* in_sizes, int n_in,
                              void* d_out, int out_size) {
    const float* pred  = (const float*)d_in[0];
    const float* gt    = (const float*)d_in[1];
    const float* am    = (const float*)d_in[2];
    const int*   batch = (const int*)d_in[3];
    const int*   chain = (const int*)d_in[4];
    float* out = (float*)d_out;

    fused_kernel<<<NFAPE + NLDDT, 256>>>(pred, gt, am, batch, chain, out);
}

// round 15
// speedup vs baseline: 1.4292x; 1.4292x over previous
#include <cuda_runtime.h>

#define LN 2
#define NR 768
#define NA 14
#define TJ 32                       // j per block
#define TI 64                       // i per block (2 passes of 32)
#define NPASS (TI / 32)             // 2
#define NTJ (NR / TJ)               // 24
#define NTI (NR / TI)               // 12
#define NFAPE (NTI * NTJ * LN)      // 576 fape blocks
#define NLDDT 96                    // 96 lddt blocks x 8 rows (scheduled FIRST)
#define ROWS_PER_LDDT (NR / NLDDT)  // 8

// output layout: fape_loss[2], rotamer_loss[2], final_ae[768*768], rotamer_error[-1][768], lddt[768]
#define OFF_AE   4
#define OFF_RE   (4 + NR * NR)
#define OFF_LDDT (OFF_RE + NR)

// ---- device scratch (zero-initialized at load; re-zeroed by last block every run) ----
__device__ float    g_acc[9];   // intra0,intra1,inter0,inter1,cnt_s,cnt_o,diag0,diag1,nres
__device__ unsigned g_cnt;      // fape blocks done

__device__ __forceinline__ float sqrt_approx(float x) {
    float r; asm("sqrt.approx.f32 %0, %1;" : "=f"(r) : "f"(x)); return r;
}
__device__ __forceinline__ float rsqrt_approx(float x) {
    float r; asm("rsqrt.approx.f32 %0, %1;" : "=f"(r) : "f"(x)); return r;
}
__device__ __forceinline__ float warp_sum(float v) {
#pragma unroll
    for (int o = 16; o > 0; o >>= 1) v += __shfl_down_sync(0xffffffffu, v, o);
    return v;
}

__device__ __forceinline__ void make_frame(const float n[3], const float ca[3], const float c[3],
                                           float e1[3], float e2[3], float e3[3]) {
    e1[0] = c[0] - ca[0]; e1[1] = c[1] - ca[1]; e1[2] = c[2] - ca[2];
    float s1 = e1[0]*e1[0] + e1[1]*e1[1] + e1[2]*e1[2];
    float i1 = rsqrt_approx(fmaxf(s1, 1e-6f));
    e1[0] *= i1; e1[1] *= i1; e1[2] *= i1;
    float v2[3] = { n[0]-ca[0], n[1]-ca[1], n[2]-ca[2] };
    float dt = e1[0]*v2[0] + e1[1]*v2[1] + e1[2]*v2[2];
    e2[0] = v2[0] - dt*e1[0]; e2[1] = v2[1] - dt*e1[1]; e2[2] = v2[2] - dt*e1[2];
    float s2 = e2[0]*e2[0] + e2[1]*e2[1] + e2[2]*e2[2];
    float i2 = rsqrt_approx(fmaxf(s2, 1e-6f));
    e2[0] *= i2; e2[1] *= i2; e2[2] *= i2;
    e3[0] = e1[1]*e2[2] - e1[2]*e2[1];
    e3[1] = e1[2]*e2[0] - e1[0]*e2[2];
    e3[2] = e1[0]*e2[1] - e1[1]*e2[0];
}

__device__ __forceinline__ void compute_Qo(const float* __restrict__ pred,
                                           const float* __restrict__ gt,
                                           int l, int i, float* dst /*12 floats*/) {
    const float* gb = gt + (size_t)i * NA * 3;
    float gn[3]  = { gb[0], gb[1], gb[2] };
    float gca[3] = { gb[3], gb[4], gb[5] };
    float gc[3]  = { gb[6], gb[7], gb[8] };
    float e1g[3], e2g[3], e3g[3];
    make_frame(gn, gca, gc, e1g, e2g, e3g);

    const float* pb = pred + (size_t)(l * NR + i) * NA * 3;
    float pn[3]  = { pb[0], pb[1], pb[2] };
    float pca[3] = { pb[3], pb[4], pb[5] };
    float pc[3]  = { pb[6], pb[7], pb[8] };
    float e1p[3], e2p[3], e3p[3];
    make_frame(pn, pca, pc, e1p, e2p, e3p);

#pragma unroll
    for (int d = 0; d < 3; d++) {
        float q0 = e1p[d]*e1g[0] + e2p[d]*e2g[0] + e3p[d]*e3g[0];
        float q1 = e1p[d]*e1g[1] + e2p[d]*e2g[1] + e3p[d]*e3g[1];
        float q2 = e1p[d]*e1g[2] + e2p[d]*e2g[2] + e3p[d]*e3g[2];
        dst[3*d+0] = q0; dst[3*d+1] = q1; dst[3*d+2] = q2;
        dst[9 + d] = pca[d] - (q0*gca[0] + q1*gca[1] + q2*gca[2]);
    }
}

__device__ __forceinline__ int atom_bits(const float* __restrict__ am, int i) {
    const float2* r = (const float2*)(am + (size_t)i * NA);
    int bits = 0;
#pragma unroll
    for (int k = 0; k < 7; k++) {
        float2 f = r[k];
        if (f.x > 0.f) bits |= (1 << (2 * k));
        if (f.y > 0.f) bits |= (1 << (2 * k + 1));
    }
    return bits;
}

__device__ __forceinline__ void fape_done(float* __restrict__ out) {
    __threadfence();
    unsigned done = atomicAdd(&g_cnt, 1u);
    if (done == NFAPE - 1) {
        float nres = fmaxf(g_acc[8], 1e-6f);
        float invCS = 0.1f / fmaxf(g_acc[4], 1e-6f);
        float invCO = 0.1f / fmaxf(g_acc[5], 1e-6f);
        out[0] = g_acc[0] * invCS + g_acc[2] * invCO;  // fape_loss[0]
        out[1] = g_acc[1] * invCS + g_acc[3] * invCO;  // fape_loss[1]
        out[2] = g_acc[6] / nres;                      // rotamer_loss[0]
        out[3] = g_acc[7] / nres;                      // rotamer_loss[1]
#pragma unroll
        for (int k = 0; k < 9; k++) g_acc[k] = 0.f;    // reset for next replay
        __threadfence();
        g_cnt = 0u;
    }
}

// ---- single fused kernel: blocks [0,96) = lddt (first: tail becomes fape mix),
// blocks [96, 96+576) = fape (64i x 32j x one l) ----
__global__ __launch_bounds__(256, 3) void fused_kernel(const float* __restrict__ pred,
                                                       const float* __restrict__ gt,
                                                       const float* __restrict__ am,
                                                       const int* __restrict__ batch,
                                                       const int* __restrict__ chain,
                                                       float* __restrict__ out) {
    const int tid = threadIdx.x;
    const int tx = tid & 31, ty = tid >> 5;

    if (blockIdx.x < NLDDT) {
        // ================= lDDT: 96 blocks x 8 rows =================
        const int b = blockIdx.x;
        __shared__ float sg[NR][3];
        __shared__ float sp[NR][3];
        __shared__ int   srm[NR];
        __shared__ float lred[8][2];
        for (int j = tid; j < NR; j += 256) {
            const float* gp = gt + ((size_t)j * NA + 1) * 3;
            sg[j][0] = gp[0]; sg[j][1] = gp[1]; sg[j][2] = gp[2];
            const float* pp = pred + ((size_t)(1 * NR + j) * NA + 1) * 3;  // pred[-1]
            sp[j][0] = pp[0]; sp[j][1] = pp[1]; sp[j][2] = pp[2];
            srm[j] = (atom_bits(am, j) != 0);
        }
        __syncthreads();

        const int i0 = b * ROWS_PER_LDDT;
#pragma unroll
        for (int r = 0; r < ROWS_PER_LDDT; r++) {
            const int i = i0 + r;
            const float gix = sg[i][0], giy = sg[i][1], giz = sg[i][2];
            const float pix = sp[i][0], piy = sp[i][1], piz = sp[i][2];
            float suml = 0.f, cnt = 0.f;
            if (srm[i]) {
                for (int j = tid; j < NR; j += 256) {
                    if (j == i || !srm[j]) continue;
                    float dx = gix - sg[j][0], dy = giy - sg[j][1], dz = giz - sg[j][2];
                    float gd = sqrt_approx(fmaxf(dx*dx + dy*dy + dz*dz, 1e-6f));
                    if (gd < 15.f) {
                        float ex = pix - sp[j][0], ey = piy - sp[j][1], ez = piz - sp[j][2];
                        float d = sqrt_approx(fmaxf(ex*ex + ey*ey + ez*ez, 1e-6f));
                        float derr = fabsf(gd - d);
                        int c = (derr < 0.5f) + (derr < 1.0f) + (derr < 2.0f) + (derr < 4.0f);
                        suml += 0.25f * (float)c;
                        cnt  += 1.f;
                    }
                }
            }
            float v0 = warp_sum(suml), v1 = warp_sum(cnt);
            if (tx == 0) { lred[ty][0] = v0; lred[ty][1] = v1; }
            __syncthreads();
            if (tid == 0) {
                float s = 0.f, c = 0.f;
#pragma unroll
                for (int w = 0; w < 8; w++) { s += lred[w][0]; c += lred[w][1]; }
                out[OFF_LDDT + i] = s / fmaxf(c, 1e-6f);
            }
            __syncthreads();
        }
        return;
    }

    // ================= FAPE super-tile: 64 i x 32 j, one l =================
    const int b = blockIdx.x - NLDDT;
    const int l = b / (NTI * NTJ);
    const int t = b % (NTI * NTJ);
    const int i0 = (t / NTJ) * TI, j0 = (t % NTJ) * TJ;
    float* out_ae = out + OFF_AE;

    // uniform loads for skip decisions (L1 broadcast, no barrier); batch sorted
    const int bj0 = batch[j0], bj1 = batch[j0 + TJ - 1];
    const bool skipA = (batch[i0] > bj1)      || (bj0 > batch[i0 + 31]);
    const bool skipB = (batch[i0 + 32] > bj1) || (bj0 > batch[i0 + TI - 1]);

    if (skipA && skipB) {
        if (l == 0 && j0 == 0 && tid < 32) {   // nres for both halves
            float n = ((atom_bits(am, i0 + tid) != 0) ? 1.f : 0.f)
                    + ((atom_bits(am, i0 + 32 + tid) != 0) ? 1.f : 0.f);
            n = warp_sum(n);
            if (tid == 0) atomicAdd(&g_acc[8], n);
        }
        if (l == 1) {
#pragma unroll
            for (int r = 0; r < 8; r++)
                out_ae[(size_t)(i0 + ty + 8 * r) * NR + (j0 + tx)] = 0.f;
        }
        if (tid == 0) fape_done(out);
        return;
    }

    __shared__ float4 sP[TJ * 15];
    __shared__ float4 sG[TJ * 15];
    __shared__ float  sQ[TI * 12];
    __shared__ int    sBatI[TI], sBatJ[TJ], sBitI[TI], sBitJ[TJ], sChI[TI], sChJ[TJ];
    __shared__ float  sred[8][5];

    if (tid < TI) {
        compute_Qo(pred, gt, l, i0 + tid, &sQ[tid * 12]);
        sBatI[tid] = batch[i0 + tid];
        sChI[tid]  = chain[i0 + tid];
        sBitI[tid] = atom_bits(am, i0 + tid);
    } else if (tid < TI + TJ) {
        int u = tid - TI;
        sBatJ[u] = batch[j0 + u];
        sChJ[u]  = chain[j0 + u];
        sBitJ[u] = atom_bits(am, j0 + u);
    }
    for (int u = tid - (TI + TJ); u >= 0 && u < TJ * NA; u += 256 - TI - TJ) {
        int j = u / NA, a = u % NA;
        const float* pp = pred + ((size_t)(l * NR + j0 + j) * NA + a) * 3;
        sP[j * 15 + a] = make_float4(pp[0], pp[1], pp[2], 0.f);
        const float* gp = gt + ((size_t)(j0 + j) * NA + a) * 3;
        sG[j * 15 + a] = make_float4(gp[0], gp[1], gp[2], 0.f);
    }
    __syncthreads();

    // nres contribution (12 blocks: l==0, j_tile==0)
    if (l == 0 && j0 == 0 && tid < 32) {
        float n = ((sBitI[tid] != 0) ? 1.f : 0.f) + ((sBitI[32 + tid] != 0) ? 1.f : 0.f);
        n = warp_sum(n);
        if (tid == 0) atomicAdd(&g_acc[8], n);
    }

    const int batJ = sBatJ[tx], bitJ = sBitJ[tx], chJ = sChJ[tx];
    float pIntra = 0.f, pInter = 0.f, pCntS = 0.f, pCntO = 0.f, pDiag = 0.f;

#pragma unroll 1
    for (int pass = 0; pass < NPASS; pass++) {
        if (pass == 0 ? skipA : skipB) {
            if (l == 1) {
#pragma unroll
                for (int r = 0; r < 4; r++)
                    out_ae[(size_t)(i0 + 32 * pass + ty + 8 * r) * NR + (j0 + tx)] = 0.f;
            }
            continue;
        }
        const int base = 32 * pass;

        float q[4][12];
        unsigned mb[4];
#pragma unroll
        for (int r = 0; r < 4; r++) {
            const int row = base + ty + 8 * r;
#pragma unroll
            for (int k = 0; k < 12; k++) q[r][k] = sQ[row * 12 + k];
            mb[r] = (sBatI[row] == batJ) ? (unsigned)(sBitI[row] & bitJ) : 0u;
        }

        float se[4] = {0.f, 0.f, 0.f, 0.f};
#pragma unroll
        for (int a = 0; a < NA; a++) {
            const float4 g = sG[tx * 15 + a];
            const float4 p = sP[tx * 15 + a];
#pragma unroll
            for (int r = 0; r < 4; r++) {
                float w0 = fmaf(q[r][0], g.x, fmaf(q[r][1], g.y, fmaf(q[r][2], g.z, q[r][9])));
                float w1 = fmaf(q[r][3], g.x, fmaf(q[r][4], g.y, fmaf(q[r][5], g.z, q[r][10])));
                float w2 = fmaf(q[r][6], g.x, fmaf(q[r][7], g.y, fmaf(q[r][8], g.z, q[r][11])));
                float d0 = p.x - w0, d1 = p.y - w1, d2 = p.z - w2;
                float n2 = fmaf(d0, d0, fmaf(d1, d1, d2 * d2));
                float err = sqrt_approx(fmaxf(n2, 1e-6f));
                // masked accumulate: err >= 0, so bitwise AND with sign-extended bit is exact
                unsigned sm = (unsigned)(((int)(mb[r] << (31 - a))) >> 31);
                se[r] += __uint_as_float(__float_as_uint(err) & sm);
            }
        }

#pragma unroll
        for (int r = 0; r < 4; r++) {
            const int row = base + ty + 8 * r;
            const int i = i0 + row, j = j0 + tx;
            float fape = __fdividef(se[r], fmaxf((float)__popc(mb[r]), 1e-6f));
            if (l == 1) out_ae[(size_t)i * NR + j] = fape;
            if (mb[r] != 0u) {
                float clip = fminf(fape, 10.f);
                if (sChI[row] == chJ) { pIntra += clip; pCntS += 1.f; }
                else                  { pInter += clip; pCntO += 1.f; }
            }
            if (i == j) {
                pDiag += fape;
                if (l == 1) out[OFF_RE + i] = fape;
            }
        }
    }

    float vals[5] = { pIntra, pInter, pCntS, pCntO, pDiag };
#pragma unroll
    for (int k = 0; k < 5; k++) {
        float v = warp_sum(vals[k]);
        if (tx == 0) sred[ty][k] = v;
    }
    __syncthreads();
    if (tid < 5) {
        float v = 0.f;
#pragma unroll
        for (int w = 0; w < 8; w++) v += sred[w][tid];
        if (tid == 0) atomicAdd(&g_acc[0 + l], v);
        else if (tid == 1) atomicAdd(&g_acc[2 + l], v);
        else if (tid == 2) { if (l == 0) atomicAdd(&g_acc[4], v); }
        else if (tid == 3) { if (l == 0) atomicAdd(&g_acc[5], v); }
        else atomicAdd(&g_acc[6 + l], v);
    }

    __syncthreads();
    if (tid == 0) fape_done(out);
}

extern "C" void kernel_launch(void* const* d_in, const int* in_sizes, int n_in,
                              void* d_out, int out_size) {
    const float* pred  = (const float*)d_in[0];
    const float* gt    = (const float*)d_in[1];
    const float* am    = (const float*)d_in[2];
    const int*   batch = (const int*)d_in[3];
    const int*   chain = (const int*)d_in[4];
    float* out = (float*)d_out;

    fused_kernel<<<NFAPE + NLDDT, 256>>>(pred, gt, am, batch, chain, out);
}